// round 2
// baseline (speedup 1.0000x reference)
#include <cuda_runtime.h>
#include <math.h>

// Problem constants (shapes fixed by the dataset)
#define NN 50000
#define NE 800000
#define D0 64   // x features
#define D1 96   // hidden
#define D2 64   // out

// ---------------- scratch (device globals: no allocation allowed) ----------
__device__ int   g_is64;
__device__ int   g_src[NE];
__device__ int   g_dst[NE];
__device__ int   g_csr[NE];
__device__ int   g_cnt[NN];
__device__ int   g_row[NN + 1];
__device__ int   g_cur[NN];
__device__ float g_dis[NN];
__device__ float g_hs1[NN * D1];  // (x@W1)*dis[row]
__device__ float g_h  [NN * D1];  // relu(layer1)
__device__ float g_hs2[NN * D2];  // (h@W2)*dis[row]

// ---------------- small setup kernels --------------------------------------

__global__ void k_zero_cnt() {
    int i = blockIdx.x * blockDim.x + threadIdx.x;
    if (i < NN) g_cnt[i] = 0;
}

// Detect whether edge_index is int64 or int32. Values are in [0, 50000), so if
// the buffer is little-endian int64 every odd 32-bit word is 0. For int32 data
// the odd words are themselves random edge values — the chance that 1024 of
// them are all zero is (1/50000)^1024 ~ 0.
__global__ void k_detect(const int* __restrict__ e) {
    __shared__ int nz;
    if (threadIdx.x == 0) nz = 0;
    __syncthreads();
    int local = 0;
    for (int i = threadIdx.x; i < 1024; i += blockDim.x)
        local |= e[2 * i + 1];
    if (local) atomicOr(&nz, 1);
    __syncthreads();
    if (threadIdx.x == 0) g_is64 = (nz == 0) ? 1 : 0;
}

// Convert edge list to int32 and histogram in-degrees.
__global__ void k_convert(const void* __restrict__ ep) {
    int e = blockIdx.x * blockDim.x + threadIdx.x;
    if (e >= NE) return;
    int s, d;
    if (g_is64) {
        const long long* p = (const long long*)ep;
        s = (int)p[e];
        d = (int)p[NE + e];
    } else {
        const int* p = (const int*)ep;
        s = p[e];
        d = p[NE + e];
    }
    g_src[e] = s;
    g_dst[e] = d;
    atomicAdd(&g_cnt[d], 1);
}

__global__ void k_dis() {
    int i = blockIdx.x * blockDim.x + threadIdx.x;
    if (i < NN) g_dis[i] = rsqrtf((float)g_cnt[i] + 1.0f);
}

// Single-block exclusive scan of g_cnt -> g_row / g_cur. 1024 threads,
// 49 elements per thread (serial), Hillis-Steele block scan of partials.
__global__ void k_scan() {
    __shared__ int sums[1024];
    const int CH = (NN + 1023) / 1024;  // 49
    int t = threadIdx.x;
    int base = t * CH;
    int s = 0;
    for (int i = 0; i < CH; i++) {
        int idx = base + i;
        if (idx < NN) s += g_cnt[idx];
    }
    sums[t] = s;
    __syncthreads();
    for (int off = 1; off < 1024; off <<= 1) {
        int v = sums[t];
        int add = (t >= off) ? sums[t - off] : 0;
        __syncthreads();
        sums[t] = v + add;
        __syncthreads();
    }
    int run = (t == 0) ? 0 : sums[t - 1];
    for (int i = 0; i < CH; i++) {
        int idx = base + i;
        if (idx < NN) {
            g_row[idx] = run;
            g_cur[idx] = run;
            run += g_cnt[idx];
        }
    }
    if (t == 1023) g_row[NN] = sums[1023];
}

__global__ void k_scatter() {
    int e = blockIdx.x * blockDim.x + threadIdx.x;
    if (e >= NE) return;
    int pos = atomicAdd(&g_cur[g_dst[e]], 1);
    g_csr[pos] = g_src[e];
}

// ---------------- GEMM: HS[row][c] = dis[row] * sum_k X[row][k]*W[k][c] -----
// Block = 256 threads = 8 warps, 32 rows per block (4 rows per warp),
// W (IN x OUT <= 24KB) and 32 rows of X staged in shared.
// Lane l computes output columns l, l+32, (l+64...). Conflict-free LDS.
template <int IN, int OUT>
__global__ void k_gemm(const float* __restrict__ X, const float* __restrict__ W,
                       float* __restrict__ HS) {
    constexpr int CPL = OUT / 32;
    __shared__ float Ws[IN * OUT];
    __shared__ float Xs[32 * IN];
    int t = threadIdx.x;
    for (int i = t; i < IN * OUT; i += 256) Ws[i] = W[i];
    int row0 = blockIdx.x * 32;
    for (int i = t; i < 32 * IN; i += 256) {
        int r = i / IN, k = i % IN;
        int gr = row0 + r;
        Xs[i] = (gr < NN) ? X[gr * IN + k] : 0.0f;
    }
    __syncthreads();

    int w = t >> 5, lane = t & 31;
    int rbase = w * 4;
    float acc[4][CPL];
#pragma unroll
    for (int r = 0; r < 4; r++)
#pragma unroll
        for (int c = 0; c < CPL; c++) acc[r][c] = 0.0f;

#pragma unroll 8
    for (int k = 0; k < IN; k++) {
        float wv[CPL];
#pragma unroll
        for (int c = 0; c < CPL; c++) wv[c] = Ws[k * OUT + lane + 32 * c];
#pragma unroll
        for (int r = 0; r < 4; r++) {
            float xv = Xs[(rbase + r) * IN + k];
#pragma unroll
            for (int c = 0; c < CPL; c++) acc[r][c] = fmaf(xv, wv[c], acc[r][c]);
        }
    }

#pragma unroll
    for (int r = 0; r < 4; r++) {
        int gr = row0 + rbase + r;
        if (gr < NN) {
            float d = g_dis[gr];
#pragma unroll
            for (int c = 0; c < CPL; c++)
                HS[gr * OUT + lane + 32 * c] = acc[r][c] * d;
        }
    }
}

// ---------------- Aggregation: one warp per node ---------------------------
// out[i][f] = act( dis[i]*(HS[i][f] + sum_{e: dst=i} HS[src_e][f]) + b[f] )
// ACT: 0 = relu, 1 = sigmoid
// 4-deep gather pipeline: 4 independent src rows in flight -> MLP_eff >= 4*CPL.
template <int F, int ACT>
__global__ void k_agg(const float* __restrict__ HS, const float* __restrict__ b,
                      float* __restrict__ OUT) {
    int warp = (blockIdx.x * blockDim.x + threadIdx.x) >> 5;
    int lane = threadIdx.x & 31;
    if (warp >= NN) return;
    constexpr int CPL = F / 32;

    float acc[CPL];
#pragma unroll
    for (int c = 0; c < CPL; c++) acc[c] = HS[warp * F + lane + 32 * c];  // self loop

    int beg = g_row[warp], end = g_row[warp + 1];
    int j = beg;
    for (; j + 3 < end; j += 4) {
        int s0 = g_csr[j + 0];
        int s1 = g_csr[j + 1];
        int s2 = g_csr[j + 2];
        int s3 = g_csr[j + 3];
        float v0[CPL], v1[CPL], v2[CPL], v3[CPL];
#pragma unroll
        for (int c = 0; c < CPL; c++) v0[c] = HS[s0 * F + lane + 32 * c];
#pragma unroll
        for (int c = 0; c < CPL; c++) v1[c] = HS[s1 * F + lane + 32 * c];
#pragma unroll
        for (int c = 0; c < CPL; c++) v2[c] = HS[s2 * F + lane + 32 * c];
#pragma unroll
        for (int c = 0; c < CPL; c++) v3[c] = HS[s3 * F + lane + 32 * c];
#pragma unroll
        for (int c = 0; c < CPL; c++)
            acc[c] += (v0[c] + v1[c]) + (v2[c] + v3[c]);
    }
    for (; j < end; j++) {
        int s0 = g_csr[j];
#pragma unroll
        for (int c = 0; c < CPL; c++) acc[c] += HS[s0 * F + lane + 32 * c];
    }

    float d = g_dis[warp];
#pragma unroll
    for (int c = 0; c < CPL; c++) {
        float v = d * acc[c] + b[lane + 32 * c];
        if (ACT == 0)
            v = fmaxf(v, 0.0f);
        else
            v = 1.0f / (1.0f + expf(-v));
        OUT[warp * F + lane + 32 * c] = v;
    }
}

// Thin wrappers so kernels can use device-global scratch without the host
// needing cudaGetSymbolAddress (keeps kernel_launch to pure launches).
__global__ void k_gemm1(const float* __restrict__ X, const float* __restrict__ W) {
    // forwarder not used; see direct template launches below
}

extern "C" void kernel_launch(void* const* d_in, const int* in_sizes, int n_in,
                              void* d_out, int out_size) {
    const float* x  = (const float*)d_in[0];
    const void*  ei = d_in[1];
    const float* W1 = (const float*)d_in[2];
    const float* b1 = (const float*)d_in[3];
    const float* W2 = (const float*)d_in[4];
    const float* b2 = (const float*)d_in[5];
    float* out = (float*)d_out;

    const int TB = 256;
    // graph/CSR construction (every call: must be deterministic work)
    k_zero_cnt<<<(NN + TB - 1) / TB, TB>>>();
    k_detect<<<1, 256>>>((const int*)ei);
    k_convert<<<(NE + TB - 1) / TB, TB>>>(ei);
    k_dis<<<(NN + TB - 1) / TB, TB>>>();
    k_scan<<<1, 1024>>>();
    k_scatter<<<(NE + TB - 1) / TB, TB>>>();

    // layer 1: hs1 = (x @ W1) * dis ; h = relu(dis*(hs1_self + sum) + b1)
    k_gemm<D0, D1><<<(NN + 31) / 32, 256>>>(x, W1, g_hs1);
    k_agg<D1, 0><<<(NN * 32 + TB - 1) / TB, TB>>>(g_hs1, b1, g_h);

    // layer 2: hs2 = (h @ W2) * dis ; out = sigmoid(dis*(hs2_self + sum) + b2)
    k_gemm<D1, D2><<<(NN + 31) / 32, 256>>>(g_h, W2, g_hs2);
    k_agg<D2, 1><<<(NN * 32 + TB - 1) / TB, TB>>>(g_hs2, b2, out);
}